// round 3
// baseline (speedup 1.0000x reference)
#include <cuda_runtime.h>
#include <cstdint>
#include <cstddef>

// Problem constants
#define BB 4
#define LL 4096
#define DD 1024
#define HH 16
#define HDIM 64
#define KSEL 1024
#define ATT_SCALE 0.125f   // 1/sqrt(64)

// ---------------------------------------------------------------------------
// Device scratch (static __device__ arrays: allocation-free per harness rules)
// ---------------------------------------------------------------------------
__device__ float g_scores[BB * LL];
__device__ int   g_idx[BB * KSEL];
__device__ float g_qb[(size_t)BB * KSEL * DD];
__device__ float g_kb[(size_t)BB * KSEL * DD];
__device__ float g_vb[(size_t)BB * KSEL * DD];
__device__ float g_ob[(size_t)BB * KSEL * DD];

// ---------------------------------------------------------------------------
// 1) Router: scores[b][l] = dot(x[b,l,:], w_router)   (bias is rank-invariant)
//    One warp per token, float4 loads.
// ---------------------------------------------------------------------------
__global__ void __launch_bounds__(256) router_kernel(const float* __restrict__ x,
                                                     const float* __restrict__ w)
{
    int warp = (blockIdx.x * blockDim.x + threadIdx.x) >> 5;
    int lane = threadIdx.x & 31;
    if (warp >= BB * LL) return;
    const float4* xr = (const float4*)(x + (size_t)warp * DD);
    const float4* wr = (const float4*)w;
    float s = 0.f;
#pragma unroll
    for (int i = lane; i < DD / 4; i += 32) {
        float4 a = xr[i], b = wr[i];
        s += a.x * b.x + a.y * b.y + a.z * b.z + a.w * b.w;
    }
#pragma unroll
    for (int o = 16; o; o >>= 1) s += __shfl_xor_sync(0xffffffffu, s, o);
    if (lane == 0) g_scores[warp] = s;
}

// ---------------------------------------------------------------------------
// 2) Top-K via full bitonic sort of 4096 (score desc, index asc) per batch.
//    Key = (~ord(score) << 32) | idx, ascending sort  ==>  jax.lax.top_k order.
// ---------------------------------------------------------------------------
__global__ void __launch_bounds__(1024) topk_kernel()
{
    __shared__ unsigned long long key[LL];
    const int b = blockIdx.x;
    const int tid = threadIdx.x;

    for (int i = tid; i < LL; i += 1024) {
        unsigned u = __float_as_uint(g_scores[b * LL + i]);
        u = (u & 0x80000000u) ? ~u : (u | 0x80000000u); // monotone map (ascending)
        unsigned inv = ~u;                              // ascending inv == descending score
        key[i] = ((unsigned long long)inv << 32) | (unsigned)i;
    }
    __syncthreads();

    for (int k = 2; k <= LL; k <<= 1) {
        for (int j = k >> 1; j > 0; j >>= 1) {
            for (int t = tid; t < LL; t += 1024) {
                int ixj = t ^ j;
                if (ixj > t) {
                    unsigned long long a = key[t], c = key[ixj];
                    bool up = ((t & k) == 0);
                    if ((a > c) == up) { key[t] = c; key[ixj] = a; }
                }
            }
            __syncthreads();
        }
    }
    if (tid < KSEL)
        g_idx[b * KSEL + tid] = (int)(key[tid] & 0xFFFFFFFFu);
}

// ---------------------------------------------------------------------------
// Shared 128x128x16 fp32 SIMT GEMM tile (256 threads, 8x8 microtile).
// Optional row-gather on A, optional row-scatter on C. M=N=K=1024, lda=ldc=DD.
// ---------------------------------------------------------------------------
__device__ __forceinline__ void gemm_128x128(const float* __restrict__ A,
                                             const int*   __restrict__ a_rows,
                                             const float* __restrict__ W,
                                             float*       __restrict__ C,
                                             const int*   __restrict__ c_rows)
{
    __shared__ float As[16][128];
    __shared__ float Bs[16][128];

    const int m0 = blockIdx.y * 128;
    const int n0 = blockIdx.x * 128;
    const int tid = threadIdx.x;

    const int lrow = tid >> 1;          // 0..127 (A row within tile)
    const int lk   = (tid & 1) << 3;    // 0 or 8
    int arow_idx = m0 + lrow;
    if (a_rows) arow_idx = a_rows[arow_idx];
    const float* arow = A + (size_t)arow_idx * DD;

    const int bkr = tid >> 5;           // 0..7
    const int bnc = (tid & 31) << 2;    // 0..124 step 4

    const int ty = tid >> 4;            // 0..15 -> rows ty*8..+7
    const int tx = tid & 15;            // 0..15 -> cols tx*8..+7

    float acc[8][8];
#pragma unroll
    for (int i = 0; i < 8; i++)
#pragma unroll
        for (int j = 0; j < 8; j++) acc[i][j] = 0.f;

    for (int k0 = 0; k0 < DD; k0 += 16) {
        float4 a0 = *(const float4*)(arow + k0 + lk);
        float4 a1 = *(const float4*)(arow + k0 + lk + 4);
        float4 b0 = *(const float4*)(W + (size_t)(k0 + bkr) * DD + n0 + bnc);
        float4 b1 = *(const float4*)(W + (size_t)(k0 + bkr + 8) * DD + n0 + bnc);

        As[lk + 0][lrow] = a0.x; As[lk + 1][lrow] = a0.y;
        As[lk + 2][lrow] = a0.z; As[lk + 3][lrow] = a0.w;
        As[lk + 4][lrow] = a1.x; As[lk + 5][lrow] = a1.y;
        As[lk + 6][lrow] = a1.z; As[lk + 7][lrow] = a1.w;
        *(float4*)&Bs[bkr][bnc]     = b0;
        *(float4*)&Bs[bkr + 8][bnc] = b1;
        __syncthreads();

#pragma unroll
        for (int kk = 0; kk < 16; kk++) {
            float4 af0 = *(const float4*)&As[kk][ty * 8];
            float4 af1 = *(const float4*)&As[kk][ty * 8 + 4];
            float4 bf0 = *(const float4*)&Bs[kk][tx * 8];
            float4 bf1 = *(const float4*)&Bs[kk][tx * 8 + 4];
            float av[8] = {af0.x, af0.y, af0.z, af0.w, af1.x, af1.y, af1.z, af1.w};
            float bv[8] = {bf0.x, bf0.y, bf0.z, bf0.w, bf1.x, bf1.y, bf1.z, bf1.w};
#pragma unroll
            for (int i = 0; i < 8; i++)
#pragma unroll
                for (int j = 0; j < 8; j++)
                    acc[i][j] = fmaf(av[i], bv[j], acc[i][j]);
        }
        __syncthreads();
    }

#pragma unroll
    for (int i = 0; i < 8; i++) {
        int r = m0 + ty * 8 + i;
        int crow_idx = c_rows ? c_rows[r] : r;
        float* cp = C + (size_t)crow_idx * DD + n0 + tx * 8;
        *(float4*)cp       = make_float4(acc[i][0], acc[i][1], acc[i][2], acc[i][3]);
        *(float4*)(cp + 4) = make_float4(acc[i][4], acc[i][5], acc[i][6], acc[i][7]);
    }
}

// 3) QKV projections: grid.z in [0,12): b = z/3, w = z%3. A rows gathered by idx.
__global__ void __launch_bounds__(256, 2) qkv_kernel(const float* __restrict__ x,
                                                     const float* __restrict__ wq,
                                                     const float* __restrict__ wk,
                                                     const float* __restrict__ wv)
{
    const int z = blockIdx.z;
    const int b = z / 3, w = z % 3;
    const float* W = (w == 0) ? wq : (w == 1) ? wk : wv;
    float* C = ((w == 0) ? g_qb : (w == 1) ? g_kb : g_vb) + (size_t)b * KSEL * DD;
    gemm_128x128(x + (size_t)b * LL * DD, g_idx + b * KSEL, W, C, nullptr);
}

// 5) O projection + scatter into out[b, idx[r], :]
__global__ void __launch_bounds__(256, 2) oproj_kernel(const float* __restrict__ wo,
                                                       float* __restrict__ out)
{
    const int b = blockIdx.z;
    gemm_128x128(g_ob + (size_t)b * KSEL * DD, nullptr, wo,
                 out + (size_t)b * LL * DD, g_idx + b * KSEL);
}

// ---------------------------------------------------------------------------
// 4) Flash-style causal attention: block = (qtile, head, batch), 64x64 tiles.
//    smem: Qt/Kt d-major (LDS.128 + broadcast friendly), Vs j-major, Ps padded.
// ---------------------------------------------------------------------------
#define ATT_SMEM_FLOATS (4096 * 3 + 64 * 68)
#define ATT_SMEM_BYTES  (ATT_SMEM_FLOATS * 4)

__global__ void __launch_bounds__(256) attn_kernel()
{
    extern __shared__ float sm[];
    float* Qt = sm;           // [d][r]  64x64
    float* Kt = sm + 4096;    // [d][j]  64x64
    float* Vs = sm + 8192;    // [j][c]  64x64
    float* Ps = sm + 12288;   // [r][68] padded

    const int qt  = (int)gridDim.x - 1 - (int)blockIdx.x; // long blocks launch first
    const int h   = blockIdx.y;
    const int b   = blockIdx.z;
    const int tid = threadIdx.x;
    const int ty  = tid >> 4;   // 0..15 -> rows ty*4..+3
    const int tx  = tid & 15;   // 0..15 -> cols tx*4..+3
    const int q0  = qt * 64;

    const float* qbase = g_qb + (size_t)b * KSEL * DD + h * HDIM;
    const float* kbase = g_kb + (size_t)b * KSEL * DD + h * HDIM;
    const float* vbase = g_vb + (size_t)b * KSEL * DD + h * HDIM;
    float*       obase = g_ob + (size_t)b * KSEL * DD + h * HDIM;

    // Load Q tile transposed + pre-scaled
    {
        const int r  = tid >> 2;
        const int dc = (tid & 3) << 4;
        const float* src = qbase + (size_t)(q0 + r) * DD + dc;
#pragma unroll
        for (int qd = 0; qd < 4; qd++) {
            float4 v = *(const float4*)(src + qd * 4);
            int d = dc + qd * 4;
            Qt[(d + 0) * 64 + r] = v.x * ATT_SCALE;
            Qt[(d + 1) * 64 + r] = v.y * ATT_SCALE;
            Qt[(d + 2) * 64 + r] = v.z * ATT_SCALE;
            Qt[(d + 3) * 64 + r] = v.w * ATT_SCALE;
        }
    }

    float mrow[4], lrow[4], o[4][4];
#pragma unroll
    for (int i = 0; i < 4; i++) {
        mrow[i] = -1e30f; lrow[i] = 0.f;
#pragma unroll
        for (int j = 0; j < 4; j++) o[i][j] = 0.f;
    }

    for (int kt = 0; kt <= qt; kt++) {
        __syncthreads(); // previous PV reads done before reloading Kt/Vs
        {
            const int r  = tid >> 2;
            const int dc = (tid & 3) << 4;
            const float* ks = kbase + (size_t)(kt * 64 + r) * DD + dc;
            const float* vs = vbase + (size_t)(kt * 64 + r) * DD + dc;
#pragma unroll
            for (int qd = 0; qd < 4; qd++) {
                int d = dc + qd * 4;
                float4 kv = *(const float4*)(ks + qd * 4);
                Kt[(d + 0) * 64 + r] = kv.x;
                Kt[(d + 1) * 64 + r] = kv.y;
                Kt[(d + 2) * 64 + r] = kv.z;
                Kt[(d + 3) * 64 + r] = kv.w;
                float4 vv = *(const float4*)(vs + qd * 4);
                *(float4*)&Vs[r * 64 + d] = vv;
            }
        }
        __syncthreads();

        // S = Q K^T (tile-local)
        float s[4][4];
#pragma unroll
        for (int i = 0; i < 4; i++)
#pragma unroll
            for (int j = 0; j < 4; j++) s[i][j] = 0.f;

#pragma unroll 16
        for (int d = 0; d < 64; d++) {
            float4 qa = *(const float4*)&Qt[d * 64 + ty * 4];
            float4 ka = *(const float4*)&Kt[d * 64 + tx * 4];
            s[0][0] = fmaf(qa.x, ka.x, s[0][0]); s[0][1] = fmaf(qa.x, ka.y, s[0][1]);
            s[0][2] = fmaf(qa.x, ka.z, s[0][2]); s[0][3] = fmaf(qa.x, ka.w, s[0][3]);
            s[1][0] = fmaf(qa.y, ka.x, s[1][0]); s[1][1] = fmaf(qa.y, ka.y, s[1][1]);
            s[1][2] = fmaf(qa.y, ka.z, s[1][2]); s[1][3] = fmaf(qa.y, ka.w, s[1][3]);
            s[2][0] = fmaf(qa.z, ka.x, s[2][0]); s[2][1] = fmaf(qa.z, ka.y, s[2][1]);
            s[2][2] = fmaf(qa.z, ka.z, s[2][2]); s[2][3] = fmaf(qa.z, ka.w, s[2][3]);
            s[3][0] = fmaf(qa.w, ka.x, s[3][0]); s[3][1] = fmaf(qa.w, ka.y, s[3][1]);
            s[3][2] = fmaf(qa.w, ka.z, s[3][2]); s[3][3] = fmaf(qa.w, ka.w, s[3][3]);
        }

        // Causal mask on diagonal tile (q0 == kt*64, so compare locals)
        if (kt == qt) {
#pragma unroll
            for (int i = 0; i < 4; i++)
#pragma unroll
                for (int j = 0; j < 4; j++)
                    if (tx * 4 + j > ty * 4 + i) s[i][j] = -1e30f;
        }

        // Online softmax (row reductions within 16-lane tx groups)
#pragma unroll
        for (int i = 0; i < 4; i++) {
            float mx = fmaxf(fmaxf(s[i][0], s[i][1]), fmaxf(s[i][2], s[i][3]));
#pragma unroll
            for (int off = 8; off; off >>= 1)
                mx = fmaxf(mx, __shfl_xor_sync(0xffffffffu, mx, off));
            float mnew  = fmaxf(mrow[i], mx);
            float alpha = __expf(mrow[i] - mnew);
            mrow[i] = mnew;
            float ps = 0.f;
#pragma unroll
            for (int j = 0; j < 4; j++) {
                float p = __expf(s[i][j] - mnew);
                s[i][j] = p; ps += p;
            }
#pragma unroll
            for (int off = 8; off; off >>= 1)
                ps += __shfl_xor_sync(0xffffffffu, ps, off);
            lrow[i] = lrow[i] * alpha + ps;
#pragma unroll
            for (int j = 0; j < 4; j++) o[i][j] *= alpha;
            *(float4*)&Ps[(ty * 4 + i) * 68 + tx * 4] =
                make_float4(s[i][0], s[i][1], s[i][2], s[i][3]);
        }
        __syncthreads();

        // O += P @ V
#pragma unroll 8
        for (int j = 0; j < 64; j++) {
            float4 vv = *(const float4*)&Vs[j * 64 + tx * 4];
#pragma unroll
            for (int i = 0; i < 4; i++) {
                float p = Ps[(ty * 4 + i) * 68 + j];
                o[i][0] = fmaf(p, vv.x, o[i][0]);
                o[i][1] = fmaf(p, vv.y, o[i][1]);
                o[i][2] = fmaf(p, vv.z, o[i][2]);
                o[i][3] = fmaf(p, vv.w, o[i][3]);
            }
        }
    }

#pragma unroll
    for (int i = 0; i < 4; i++) {
        float inv = 1.f / lrow[i];
        float* op = obase + (size_t)(q0 + ty * 4 + i) * DD + tx * 4;
        *(float4*)op = make_float4(o[i][0] * inv, o[i][1] * inv,
                                   o[i][2] * inv, o[i][3] * inv);
    }
}

// ---------------------------------------------------------------------------
// Launch: copy-through + router -> topk -> QKV -> attention -> Oproj+scatter
// ---------------------------------------------------------------------------
extern "C" void kernel_launch(void* const* d_in, const int* in_sizes, int n_in,
                              void* d_out, int out_size)
{
    const float* x  = (const float*)d_in[0];
    const float* wr = (const float*)d_in[1];
    // d_in[2] = b_router: constant bias, rank-invariant, unused
    const float* wq = (const float*)d_in[3];
    const float* wk = (const float*)d_in[4];
    const float* wv = (const float*)d_in[5];
    const float* wo = (const float*)d_in[6];
    float* out = (float*)d_out;

    // Passthrough for unselected tokens (selected rows overwritten by oproj)
    cudaMemcpyAsync(out, x, (size_t)BB * LL * DD * sizeof(float),
                    cudaMemcpyDeviceToDevice);

    router_kernel<<<(BB * LL) / 8, 256>>>(x, wr);
    topk_kernel<<<BB, 1024>>>();
    qkv_kernel<<<dim3(8, 8, 12), 256>>>(x, wq, wk, wv);

    cudaFuncSetAttribute(attn_kernel,
                         cudaFuncAttributeMaxDynamicSharedMemorySize,
                         ATT_SMEM_BYTES);
    attn_kernel<<<dim3(16, HH, BB), 256, ATT_SMEM_BYTES>>>();

    oproj_kernel<<<dim3(8, 8, 4), 256>>>(wo, out);
}